// round 16
// baseline (speedup 1.0000x reference)
#include <cuda_runtime.h>

// Problem shape (fixed by setup_inputs): B=4, C=3, H=W=256, kernel [3,1,3,3]
#define Bn   4
#define Cc   3
#define Hh   256
#define Ww   256
#define HW   (Hh * Ww)          // 65536
#define NCH  (Bn * Cc * HW)     // 786432
#define NSC  (Bn * HW)          // 262144

// Tiling: 128 tiles of 32x64 over the [B,H,W] scalar domain -> grid = 128 blocks
#define TY   32
#define TX   64
#define SDW  68                 // d-tile width (halo 2): point (ly,lx) -> sD[(ly+2)*SDW + lx+2]
#define NBLK 128
#define NTHR 512
#define PPT  4                  // 4 CONSECUTIVE points per thread (one row segment)
#define NRING 400               // halo-ring entries: 4*68 + 32*4
#define NB_ITERS 101
#define TOLf 1e-6f

// -------- device scratch (no allocations allowed) --------
__device__ float  g_r[NCH];          // r ring published once at setup (halo seed)
__device__ float  g_apb[2][NCH];     // Ap ring, double-buffered by iteration parity
__device__ float  g_dscr[NSC];
__device__ float4 g_pd4[2][NBLK];    // (p.Ap, r.Ap, Ap.Ap, r.r) partials, parity-buffered
__device__ unsigned int g_count = 0;
__device__ unsigned int g_gen   = 0;

// -------- software grid barrier (R5/R8-proven form) --------
__device__ __forceinline__ void gsync() {
    __syncthreads();
    if (threadIdx.x == 0) {
        volatile unsigned int* vgen = &g_gen;
        unsigned int gen = *vgen;
        __threadfence();
        if (atomicAdd(&g_count, 1u) == NBLK - 1u) {
            *((volatile unsigned int*)&g_count) = 0u;
            __threadfence();
            *vgen = gen + 1u;
        } else {
            while (*vgen == gen) { __nanosleep(64); }
        }
        __threadfence();
    }
    __syncthreads();
}

// deterministic 4-way fp32 block tree reduction; results on thread 0. s: 64 floats
__device__ __forceinline__ void block_reduce4(float& a, float& b, float& c,
                                              float& d, float* s) {
#pragma unroll
    for (int o = 16; o > 0; o >>= 1) {
        a += __shfl_down_sync(0xffffffffu, a, o);
        b += __shfl_down_sync(0xffffffffu, b, o);
        c += __shfl_down_sync(0xffffffffu, c, o);
        d += __shfl_down_sync(0xffffffffu, d, o);
    }
    int w = threadIdx.x >> 5;
    if ((threadIdx.x & 31) == 0) { s[w] = a; s[16 + w] = b; s[32 + w] = c; s[48 + w] = d; }
    __syncthreads();
    if (threadIdx.x < 32) {
        bool in = threadIdx.x < (NTHR / 32);
        a = in ? s[threadIdx.x]      : 0.f;
        b = in ? s[16 + threadIdx.x] : 0.f;
        c = in ? s[32 + threadIdx.x] : 0.f;
        d = in ? s[48 + threadIdx.x] : 0.f;
#pragma unroll
        for (int o = 8; o > 0; o >>= 1) {
            a += __shfl_down_sync(0xffffffffu, a, o);
            b += __shfl_down_sync(0xffffffffu, b, o);
            c += __shfl_down_sync(0xffffffffu, c, o);
            d += __shfl_down_sync(0xffffffffu, d, o);
        }
    }
}

// identical-everywhere reduction of the 128 float4 partials (fixed order)
__device__ __forceinline__ void reduce4_arr(int par, float* sbc,
                                            float& rx, float& ry,
                                            float& rz, float& rw) {
    __syncthreads();
    if (threadIdx.x < 32) {
        float a = 0.f, b = 0.f, c = 0.f, d = 0.f;
#pragma unroll
        for (int i = 0; i < NBLK / 32; i++) {
            float4 v = __ldcg(&g_pd4[par][threadIdx.x + i * 32]);
            a += v.x; b += v.y; c += v.z; d += v.w;
        }
#pragma unroll
        for (int o = 16; o > 0; o >>= 1) {
            a += __shfl_down_sync(0xffffffffu, a, o);
            b += __shfl_down_sync(0xffffffffu, b, o);
            c += __shfl_down_sync(0xffffffffu, c, o);
            d += __shfl_down_sync(0xffffffffu, d, o);
        }
        if (threadIdx.x == 0) { sbc[0] = a; sbc[1] = b; sbc[2] = c; sbc[3] = d; }
    }
    __syncthreads();
    rx = sbc[0]; ry = sbc[1]; rz = sbc[2]; rw = sbc[3];
    __syncthreads();
}

__global__ void __launch_bounds__(NTHR, 1)
cg_kernel(const float* __restrict__ mask, const float* __restrict__ yin,
          const float* __restrict__ zin,  const float* __restrict__ bein,
          const float* __restrict__ rhop, const float* __restrict__ kern,
          float* __restrict__ xout)
{
    __shared__ __align__(16) float sD[36 * SDW];   // d tile with halo 2
    __shared__ float sRed[64];                // block_reduce staging
    __shared__ float sBc[4];                  // broadcast slots
    __shared__ float sKK[27];                 // raw 3x3x3 kernel (boundary corrections)
    __shared__ float sK5[25];                 // composed 5x5 kernel staging
    __shared__ float sHm[3][NRING];           // halo mask (loaded once)
    __shared__ float sHr[3][NRING];           // halo r shadow (recurrence-advanced)
    __shared__ float sHp[3][NRING];           // halo p shadow

    const int tid = threadIdx.x;
    const int bid = blockIdx.x;
    const float rho = rhop[0];

    // tile decomposition: 4 images x (8 row-tiles x 4 col-tiles) = 128 tiles
    const int bimg = bid >> 5;
    const int tr   = (bid >> 2) & 7;
    const int tc   = bid & 3;
    const int gy0  = tr * TY;
    const int gx0  = tc * TX;
    const int sbase = bimg * HW;          // [B,H,W] base
    const int cbase = bimg * (Cc * HW);   // [B,C,H,W] base

    // contiguous ownership: thread owns points (ly, lx0..lx0+3)
    const int ly  = tid >> 4;             // 0..31
    const int lx0 = (tid & 15) * 4;       // 0,4,...,60
    const bool rowring = (ly < 2) || (ly >= TY - 2);
    const int idxP = cbase + (gy0 + ly) * Ww + gx0 + lx0;   // point base (c=0)
    const int gy   = gy0 + ly;
    const int gxL  = gx0 + lx0;
    const bool anyEdge = (gy == 0) || (gy == Hh - 1) || (gxL == 0) || (gxL + PPT == Ww);

    // build composed 5x5 kernel: K5[u] = sum_o autocorrelation(k_o)[u]
    if (tid < 27) sKK[tid] = kern[tid];
    if (tid < 25) {
        int uy = tid / 5 - 2, ux = tid % 5 - 2;
        float s = 0.f;
        for (int o = 0; o < 3; o++)
            for (int sy = 0; sy < 3; sy++)
                for (int sx = 0; sx < 3; sx++) {
                    int by = sy + uy, bx = sx + ux;
                    if (by >= 0 && by < 3 && bx >= 0 && bx < 3)
                        s = fmaf(kern[o * 9 + sy * 3 + sx],
                                 kern[o * 9 + by * 3 + bx], s);
                }
        sK5[tid] = s;
    }

    // precomputed halo-slot geometry (threads 0..NRING-1 own one slot each)
    int soff = -1, hidx = -1;
    if (tid < NRING) {
        int ly2, lxx;
        if (tid < 272) {
            int rr4 = tid / 68;
            ly2 = (rr4 < 2) ? rr4 : rr4 + 32;  // halo rows {0,1,34,35} of 36
            lxx = tid - rr4 * 68;
        } else {
            int j2 = tid - 272;
            ly2 = 2 + (j2 >> 2);
            int c4 = j2 & 3;
            lxx = (c4 < 2) ? c4 : c4 + 64;     // halo cols {0,1,66,67} of 68
        }
        soff = ly2 * SDW + lxx;
        int gyq = gy0 + ly2 - 2, gxq = gx0 + lxx - 2;
        if ((unsigned)gyq < Hh && (unsigned)gxq < Ww)
            hidx = cbase + gyq * Ww + gxq;
    }

    // register-carried CG state
    float xv[PPT][3], rv[PPT][3], pv[PPT][3];
    float mv[PPT];                        // per-point PT(P(d_p)) of current p

    __syncthreads();                      // sK5/sKK visible
    float K5r[25];
#pragma unroll
    for (int i = 0; i < 25; i++) K5r[i] = sK5[i];

    // m = PT(P(d)) for the 4 owned points: direct 5x5 over sD (zero-padded),
    // then subtract phantom-t terms for points ON the image boundary (the
    // reference crops t=P(d) at the image, so only |v|<=1 offsets matter).
    auto get_m5 = [&](float* out) {
        float a0 = 0.f, a1 = 0.f, a2 = 0.f, a3 = 0.f;
#pragma unroll
        for (int r2 = 0; r2 < 5; r2++) {
            const float4* bp = reinterpret_cast<const float4*>(&sD[(ly + r2) * SDW + lx0]);
            float4 v0 = bp[0], v1 = bp[1];
            float f[8] = {v0.x, v0.y, v0.z, v0.w, v1.x, v1.y, v1.z, v1.w};
#pragma unroll
            for (int c2 = 0; c2 < 5; c2++) {
                float w = K5r[r2 * 5 + c2];
                a0 = fmaf(w, f[c2],     a0);
                a1 = fmaf(w, f[c2 + 1], a1);
                a2 = fmaf(w, f[c2 + 2], a2);
                a3 = fmaf(w, f[c2 + 3], a3);
            }
        }
        out[0] = a0; out[1] = a1; out[2] = a2; out[3] = a3;

        if (anyEdge) {
#pragma unroll
            for (int j = 0; j < PPT; j++) {
                int gx = gxL + j;
                if (gy != 0 && gy != Hh - 1 && gx != 0 && gx != Ww - 1) continue;
                float corr = 0.f;
#pragma unroll 1
                for (int vy = -1; vy <= 1; vy++)
#pragma unroll 1
                    for (int vx = -1; vx <= 1; vx++) {
                        int qy = gy + vy, qx = gx + vx;
                        if ((unsigned)qy < Hh && (unsigned)qx < Ww) continue;
                        int sq = (ly + 2 + vy) * SDW + lx0 + j + 2 + vx;
                        float dq[9];
#pragma unroll
                        for (int a = 0; a < 3; a++)
#pragma unroll
                            for (int b = 0; b < 3; b++)
                                dq[a * 3 + b] = sD[sq + (a - 1) * SDW + (b - 1)];
#pragma unroll 1
                        for (int o = 0; o < 3; o++) {
                            float tp = 0.f;
#pragma unroll
                            for (int t9 = 0; t9 < 9; t9++)
                                tp = fmaf(sKK[o * 9 + t9], dq[t9], tp);
                            corr = fmaf(sKK[o * 9 + (1 - vy) * 3 + (1 - vx)], tp, corr);
                        }
                    }
                out[j] -= corr;
            }
        }
    };

    // ================= setup S1: m_y = PT(P(y)); b = mask*m_y + rho*(z-beta);
    //        x_reg = b; d_x = sum_c mask*b -> g_dscr (full) =================
#pragma unroll 1
    for (int i = tid; i < 36 * 68; i += NTHR) {
        int ly2 = i / 68, lxx = i - ly2 * 68;
        int gyq = gy0 + ly2 - 2, gxq = gx0 + lxx - 2;
        float v = 0.f;
        if ((unsigned)gyq < Hh && (unsigned)gxq < Ww)
            v = yin[sbase + gyq * Ww + gxq];
        sD[i] = v;
    }
    __syncthreads();
    {
        float m4a[PPT]; get_m5(m4a);
        float dv[PPT] = {0.f, 0.f, 0.f, 0.f};
#pragma unroll
        for (int c = 0; c < 3; c++) {
            float4 mk4 = __ldg((const float4*)&mask[idxP + c * HW]);
            float4 z4  = __ldg((const float4*)&zin[idxP + c * HW]);
            float4 be4 = __ldg((const float4*)&bein[idxP + c * HW]);
            float mkj[4] = {mk4.x, mk4.y, mk4.z, mk4.w};
            float zj[4]  = {z4.x, z4.y, z4.z, z4.w};
            float bj[4]  = {be4.x, be4.y, be4.z, be4.w};
#pragma unroll
            for (int j = 0; j < PPT; j++) {
                float bval = fmaf(mkj[j], m4a[j], rho * (zj[j] - bj[j]));
                xv[j][c] = bval;
                dv[j] = fmaf(mkj[j], bval, dv[j]);
            }
        }
        *(float4*)&g_dscr[sbase + (gy0 + ly) * Ww + gx0 + lx0] =
            make_float4(dv[0], dv[1], dv[2], dv[3]);
    }
    gsync();

    // ================= setup S2: r = b - A(b); publish r ring =================
#pragma unroll 1
    for (int i = tid; i < 36 * 68; i += NTHR) {
        int ly2 = i / 68, lxx = i - ly2 * 68;
        int gyq = gy0 + ly2 - 2, gxq = gx0 + lxx - 2;
        float v = 0.f;
        if ((unsigned)gyq < Hh && (unsigned)gxq < Ww)
            v = __ldcg(&g_dscr[sbase + gyq * Ww + gxq]);
        sD[i] = v;
    }
    __syncthreads();
    {
        float m4a[PPT]; get_m5(m4a);
#pragma unroll
        for (int c = 0; c < 3; c++) {
            float4 mk4 = __ldg((const float4*)&mask[idxP + c * HW]);
            float mkj[4] = {mk4.x, mk4.y, mk4.z, mk4.w};
            float r4[4];
#pragma unroll
            for (int j = 0; j < PPT; j++) {
                float bval = xv[j][c];
                float r0 = bval - fmaf(rho, bval, mkj[j] * m4a[j]);
                rv[j][c] = r0;
                r4[j] = r0;
            }
            if (rowring) {
                *(float4*)&g_r[idxP + c * HW] = make_float4(r4[0], r4[1], r4[2], r4[3]);
            } else if (lx0 == 0) {
                g_r[idxP + c * HW]     = r4[0];
                g_r[idxP + c * HW + 1] = r4[1];
            } else if (lx0 == TX - 4) {
                g_r[idxP + c * HW + 2] = r4[2];
                g_r[idxP + c * HW + 3] = r4[3];
            }
        }
    }
    gsync();

    // seed halo shadows from the published r ring
    if (tid < NRING) {
#pragma unroll
        for (int c = 0; c < 3; c++) {
            float hm = 0.f, hr = 0.f;
            if (hidx >= 0) {
                hm = __ldg(&mask[hidx + c * HW]);
                hr = __ldcg(&g_r[hidx + c * HW]);
            }
            sHm[c][tid] = hm;
            sHr[c][tid] = hr;
            sHp[c][tid] = 0.f;
        }
    }

    // prologue: p = r (classic CG start); fill sD for the first iteration
    {
        float dv[PPT] = {0.f, 0.f, 0.f, 0.f};
#pragma unroll
        for (int c = 0; c < 3; c++) {
            float4 mk4 = __ldg((const float4*)&mask[idxP + c * HW]);
            float mkj[4] = {mk4.x, mk4.y, mk4.z, mk4.w};
#pragma unroll
            for (int j = 0; j < PPT; j++) {
                pv[j][c] = rv[j][c];
                dv[j] = fmaf(mkj[j], pv[j][c], dv[j]);
            }
        }
        *(float2*)&sD[(ly + 2) * SDW + lx0 + 2] = make_float2(dv[0], dv[1]);
        *(float2*)&sD[(ly + 2) * SDW + lx0 + 4] = make_float2(dv[2], dv[3]);
    }
    if (tid < NRING) {
        float dvh = 0.f;
        if (hidx >= 0) {
#pragma unroll
            for (int c = 0; c < 3; c++) {
                float hp = sHr[c][tid];
                sHp[c][tid] = hp;
                dvh = fmaf(sHm[c][tid], hp, dvh);
            }
        }
        sD[soff] = dvh;   // out-of-image slots stay 0 forever
    }

    // ================= CG main loop: ONE grid sync per iteration =============
    // alpha uses the TRUE crit (r.r from stored r, measured each iteration).
    // beta uses a SINGLE-STEP recurrence re-anchored to that crit. All fp32
    // (sm_103a fp64 pipe ~10x too slow — R13 lesson). Stencil = composed 5x5.
#pragma unroll 1
    for (int k = 1; k <= NB_ITERS; k++) {
        const int par = k & 1;
        float* __restrict__ apb = g_apb[par];

        __syncthreads();   // sD (interior + halo) ready

        // ---- A: m = PT(P(d)); Ap; publish Ap ring; 4 fp32 dot products ----
        {
            float m4a[PPT]; get_m5(m4a);
            mv[0] = m4a[0]; mv[1] = m4a[1]; mv[2] = m4a[2]; mv[3] = m4a[3];
            float pd = 0.f, rap = 0.f, aa = 0.f, rr = 0.f;
#pragma unroll
            for (int c = 0; c < 3; c++) {
                float4 mk4 = __ldg((const float4*)&mask[idxP + c * HW]);
                float mkj[4] = {mk4.x, mk4.y, mk4.z, mk4.w};
                float ap[4];
#pragma unroll
                for (int j = 0; j < PPT; j++) {
                    ap[j] = fmaf(rho, pv[j][c], mkj[j] * m4a[j]);
                    pd  = fmaf(pv[j][c], ap[j], pd);
                    rap = fmaf(rv[j][c], ap[j], rap);
                    aa  = fmaf(ap[j], ap[j], aa);
                    rr  = fmaf(rv[j][c], rv[j][c], rr);
                }
                if (rowring) {
                    *(float4*)&apb[idxP + c * HW] = make_float4(ap[0], ap[1], ap[2], ap[3]);
                } else if (lx0 == 0) {
                    apb[idxP + c * HW]     = ap[0];
                    apb[idxP + c * HW + 1] = ap[1];
                } else if (lx0 == TX - 4) {
                    apb[idxP + c * HW + 2] = ap[2];
                    apb[idxP + c * HW + 3] = ap[3];
                }
            }
            block_reduce4(pd, rap, aa, rr, sRed);
            if (tid == 0)
                __stcg(&g_pd4[par][bid], make_float4(pd, rap, aa, rr));
        }
        gsync();   // the ONLY grid sync in the iteration

        // ---- fused B: scalars; x,r update; p = r + beta*p; refill sD ----
        {
            float sx, sy, sz, crit;
            reduce4_arr(par, sBc, sx, sy, sz, crit);     // identical everywhere
            if (!(crit >= TOLf)) break;     // reference 'active' gating: frozen
            float alphaf = crit / sx;
            float critn = fmaf(alphaf * alphaf, sz, fmaf(-2.f * alphaf, sy, crit));
            if (critn < 0.f) critn = 0.f;   // fp32 noise guard near convergence
            float betan = critn / crit;

            float dv[PPT] = {0.f, 0.f, 0.f, 0.f};
#pragma unroll
            for (int c = 0; c < 3; c++) {
                float4 mk4 = __ldg((const float4*)&mask[idxP + c * HW]);
                float mkj[4] = {mk4.x, mk4.y, mk4.z, mk4.w};
#pragma unroll
                for (int j = 0; j < PPT; j++) {
                    float apv  = fmaf(rho, pv[j][c], mkj[j] * mv[j]);
                    xv[j][c]   = fmaf(alphaf, pv[j][c], xv[j][c]);
                    float rnew = fmaf(-alphaf, apv, rv[j][c]);
                    float pnew = fmaf(betan, pv[j][c], rnew);
                    rv[j][c] = rnew;
                    pv[j][c] = pnew;
                    dv[j] = fmaf(mkj[j], pnew, dv[j]);
                }
            }
            *(float2*)&sD[(ly + 2) * SDW + lx0 + 2] = make_float2(dv[0], dv[1]);
            *(float2*)&sD[(ly + 2) * SDW + lx0 + 4] = make_float2(dv[2], dv[3]);

            if (tid < NRING && hidx >= 0) {
                float dvh = 0.f;
#pragma unroll
                for (int c = 0; c < 3; c++) {
                    float hap = __ldcg(&apb[hidx + c * HW]);
                    float hrn = fmaf(-alphaf, hap, sHr[c][tid]);
                    float hpn = fmaf(betan, sHp[c][tid], hrn);
                    sHr[c][tid] = hrn;
                    sHp[c][tid] = hpn;
                    dvh = fmaf(sHm[c][tid], hpn, dvh);
                }
                sD[soff] = dvh;
            }
        }
        // next iteration's opening __syncthreads orders these sD writes;
        // parity buffers make the next Ap publish race-free vs B's reads.
    }

    // ================= final: write x from registers (own points) ==========
#pragma unroll
    for (int c = 0; c < 3; c++)
        *(float4*)&xout[idxP + c * HW] =
            make_float4(xv[0][c], xv[1][c], xv[2][c], xv[3][c]);
}

extern "C" void kernel_launch(void* const* d_in, const int* in_sizes, int n_in,
                              void* d_out, int out_size) {
    (void)in_sizes; (void)n_in; (void)out_size;
    cg_kernel<<<NBLK, NTHR>>>(
        (const float*)d_in[0],   // mask  [4,3,256,256]
        (const float*)d_in[1],   // y     [4,256,256]
        (const float*)d_in[2],   // z     [4,3,256,256]
        (const float*)d_in[3],   // beta  [4,3,256,256]
        (const float*)d_in[4],   // rho   scalar
        (const float*)d_in[5],   // kernel[3,1,3,3]
        (float*)d_out);          // x     [4,3,256,256]
}